// round 6
// baseline (speedup 1.0000x reference)
#include <cuda_runtime.h>
#include <cuda_bf16.h>
#include <cstdint>
#include <math.h>

#define TOKENS 8192
#define DIM    1024
#define CODES  16384
#define KSEL   8
#define NCAND  32
#define NCHUNKS 256          // CODES / 64 candidate chunks per token

// ---------------------------------------------------------------------------
// Device scratch (no allocations allowed)
// ---------------------------------------------------------------------------
__device__ float          g_c2[CODES];
__device__ __nv_bfloat16  g_Xb[(size_t)TOKENS * DIM];             // 16 MB
__device__ __nv_bfloat16  g_CBb[(size_t)CODES * DIM];             // 32 MB
__device__ float          g_pv[(size_t)TOKENS * NCHUNKS * 8];     // 64 MB
__device__ int            g_pi[(size_t)TOKENS * NCHUNKS * 8];     // 64 MB
__device__ int            g_cand[TOKENS * NCAND];
__device__ int            g_ids[TOKENS * KSEL];

// ---------------------------------------------------------------------------
// Helpers
// ---------------------------------------------------------------------------
__device__ __forceinline__ uint32_t smem_to_u32(const void* p) {
    uint32_t a;
    asm("{ .reg .u64 t; cvta.to.shared.u64 t, %1; cvt.u32.u64 %0, t; }" : "=r"(a) : "l"(p));
    return a;
}
#define SWZ128(b) ((b) ^ (((b) >> 3) & 0x70))

__device__ __forceinline__ void cp_async16(uint32_t dst, const void* src) {
    asm volatile("cp.async.cg.shared.global [%0], [%1], 16;" :: "r"(dst), "l"(src) : "memory");
}
#define LDSM_X4(r0, r1, r2, r3, addr) \
    asm volatile("ldmatrix.sync.aligned.m8n8.x4.shared.b16 {%0,%1,%2,%3}, [%4];" \
        : "=r"(r0), "=r"(r1), "=r"(r2), "=r"(r3) : "r"(addr))

__device__ __forceinline__ void mma_bf16(float* c, const uint32_t* a, const uint32_t* b) {
    asm volatile(
        "mma.sync.aligned.m16n8k16.row.col.f32.bf16.bf16.f32 "
        "{%0,%1,%2,%3}, {%4,%5,%6,%7}, {%8,%9}, {%0,%1,%2,%3};"
        : "+f"(c[0]), "+f"(c[1]), "+f"(c[2]), "+f"(c[3])
        : "r"(a[0]), "r"(a[1]), "r"(a[2]), "r"(a[3]), "r"(b[0]), "r"(b[1]));
}

// Ordering: value desc, tie -> lower index (matches jax.lax.top_k)
__device__ __forceinline__ bool better(float va, int ia, float vb, int ib) {
    return (va > vb) || (va == vb && ia < ib);
}
// Compare-exchange: better element to (v0,i0). Static-index, predication-friendly.
__device__ __forceinline__ void ce(float& v0, int& i0, float& v1, int& i1) {
    bool sw = better(v1, i1, v0, i0);
    float tv = sw ? v1 : v0; float tw = sw ? v0 : v1;
    int   ti = sw ? i1 : i0; int   tj = sw ? i0 : i1;
    v0 = tv; v1 = tw; i0 = ti; i1 = tj;
}
// Batcher 8-network (19 comparators) -> sorted desc
__device__ __forceinline__ void sort8_desc(float* v, int* ix) {
    ce(v[0],ix[0],v[1],ix[1]); ce(v[2],ix[2],v[3],ix[3]);
    ce(v[4],ix[4],v[5],ix[5]); ce(v[6],ix[6],v[7],ix[7]);
    ce(v[0],ix[0],v[2],ix[2]); ce(v[1],ix[1],v[3],ix[3]);
    ce(v[4],ix[4],v[6],ix[6]); ce(v[5],ix[5],v[7],ix[7]);
    ce(v[1],ix[1],v[2],ix[2]); ce(v[5],ix[5],v[6],ix[6]);
    ce(v[0],ix[0],v[4],ix[4]); ce(v[1],ix[1],v[5],ix[5]);
    ce(v[2],ix[2],v[6],ix[6]); ce(v[3],ix[3],v[7],ix[7]);
    ce(v[2],ix[2],v[4],ix[4]); ce(v[3],ix[3],v[5],ix[5]);
    ce(v[1],ix[1],v[2],ix[2]); ce(v[3],ix[3],v[4],ix[4]);
    ce(v[5],ix[5],v[6],ix[6]);
}
// Merge two sorted-desc 8-lists -> top-8 sorted desc into (a, ai). Static-index.
__device__ __forceinline__ void merge_top8(float* a, int* ai,
                                           const float* b, const int* bi) {
    float cv[16]; int ci[16];
    #pragma unroll
    for (int q = 0; q < 8; q++) {
        cv[q] = a[q];       ci[q] = ai[q];
        cv[8 + q] = b[7 - q]; ci[8 + q] = bi[7 - q];   // reversed -> bitonic
    }
    #pragma unroll
    for (int q = 0; q < 8; q++) ce(cv[q], ci[q], cv[q + 8], ci[q + 8]);
    // bitonic merge desc of cv[0..7]
    ce(cv[0],ci[0],cv[4],ci[4]); ce(cv[1],ci[1],cv[5],ci[5]);
    ce(cv[2],ci[2],cv[6],ci[6]); ce(cv[3],ci[3],cv[7],ci[7]);
    ce(cv[0],ci[0],cv[2],ci[2]); ce(cv[1],ci[1],cv[3],ci[3]);
    ce(cv[4],ci[4],cv[6],ci[6]); ce(cv[5],ci[5],cv[7],ci[7]);
    ce(cv[0],ci[0],cv[1],ci[1]); ce(cv[2],ci[2],cv[3],ci[3]);
    ce(cv[4],ci[4],cv[5],ci[5]); ce(cv[6],ci[6],cv[7],ci[7]);
    #pragma unroll
    for (int q = 0; q < 8; q++) { a[q] = cv[q]; ai[q] = ci[q]; }
}

// ---------------------------------------------------------------------------
// fp32 -> bf16 convert (inputs)
// ---------------------------------------------------------------------------
__global__ __launch_bounds__(256) void convX_kernel(const float* __restrict__ src) {
    size_t i = (size_t)blockIdx.x * 256 + threadIdx.x;
    float4 v = reinterpret_cast<const float4*>(src)[i];
    reinterpret_cast<__nv_bfloat162*>(g_Xb)[i * 2 + 0] = __floats2bfloat162_rn(v.x, v.y);
    reinterpret_cast<__nv_bfloat162*>(g_Xb)[i * 2 + 1] = __floats2bfloat162_rn(v.z, v.w);
}

// ---------------------------------------------------------------------------
// Fused codebook convert + c2 norm (one pass over 64 MB)
// ---------------------------------------------------------------------------
__global__ __launch_bounds__(256) void convCB_c2_kernel(const float* __restrict__ cb) {
    const int code = blockIdx.x;
    const int t = threadIdx.x;
    float4 v = reinterpret_cast<const float4*>(cb + (size_t)code * DIM)[t];
    size_t o2 = ((size_t)code * DIM + t * 4) >> 1;   // bfloat162 index
    reinterpret_cast<__nv_bfloat162*>(g_CBb)[o2 + 0] = __floats2bfloat162_rn(v.x, v.y);
    reinterpret_cast<__nv_bfloat162*>(g_CBb)[o2 + 1] = __floats2bfloat162_rn(v.z, v.w);
    float s = v.x * v.x + v.y * v.y + v.z * v.z + v.w * v.w;
    #pragma unroll
    for (int o = 16; o > 0; o >>= 1) s += __shfl_down_sync(0xffffffffu, s, o);
    __shared__ float red[8];
    if ((t & 31) == 0) red[t >> 5] = s;
    __syncthreads();
    if (t == 0) {
        float tot = 0.f;
        #pragma unroll
        for (int i = 0; i < 8; i++) tot += red[i];
        g_c2[code] = tot;
    }
}

// ---------------------------------------------------------------------------
// mma.sync bf16 GEMM + fused per-(row, 64-col chunk) top-8 candidate epilogue.
// CTA 128(M) x 256(N), 8 warps (warp tile 64x64), k-chunk 64, double buffer.
// No score matrix is materialized.
// ---------------------------------------------------------------------------
#define KC        64
#define NKC       (DIM / KC)          // 16
#define A_BYTES   (128 * 128)
#define B_BYTES   (256 * 128)
#define OFF_C2S   0
#define OFF_A0    1024
#define OFF_A1    (OFF_A0 + A_BYTES)
#define OFF_B0    (OFF_A1 + A_BYTES)
#define OFF_B1    (OFF_B0 + B_BYTES)
#define GEMM_SMEM (OFF_B1 + B_BYTES)  // 99328 bytes

__global__ __launch_bounds__(256, 1) void gemm_cand_kernel() {
    extern __shared__ char smem[];
    const uint32_t sb = smem_to_u32(smem);
    const int tid = threadIdx.x;
    const int wid = tid >> 5;
    const int lane = tid & 31;
    const int bm = blockIdx.y * 128;
    const int bn = blockIdx.x * 256;

    const int warp_m = (wid >> 2) * 64;
    const int warp_n = (wid & 3) * 64;

    if (tid < 64) {
        float4 v = *reinterpret_cast<const float4*>(g_c2 + bn + tid * 4);
        *reinterpret_cast<float4*>(smem + OFF_C2S + tid * 16) = v;
    }

    const uint32_t aoff[2] = {OFF_A0, OFF_A1};
    const uint32_t boff[2] = {OFF_B0, OFF_B1};

    auto load_chunk = [&](int c, int buf) {
        const int k0 = c * KC;
        #pragma unroll
        for (int i = 0; i < 4; i++) {
            int s = tid + i * 256;
            int row = s >> 3, seg = s & 7;
            const char* g = reinterpret_cast<const char*>(
                g_Xb + (size_t)(bm + row) * DIM + k0) + seg * 16;
            cp_async16(sb + aoff[buf] + SWZ128(row * 128 + seg * 16), g);
        }
        #pragma unroll
        for (int i = 0; i < 8; i++) {
            int s = tid + i * 256;
            int row = s >> 3, seg = s & 7;
            const char* g = reinterpret_cast<const char*>(
                g_CBb + (size_t)(bn + row) * DIM + k0) + seg * 16;
            cp_async16(sb + boff[buf] + SWZ128(row * 128 + seg * 16), g);
        }
        asm volatile("cp.async.commit_group;" ::: "memory");
    };

    float acc[4][8][4];
    #pragma unroll
    for (int mi = 0; mi < 4; mi++)
        #pragma unroll
        for (int nj = 0; nj < 8; nj++)
            #pragma unroll
            for (int e = 0; e < 4; e++) acc[mi][nj][e] = 0.f;

    const int a_row = (lane & 15);
    const int a_kb  = (lane & 16) ? 16 : 0;
    const int b_row = (lane & 7) + ((lane & 16) >> 1);
    const int b_kb  = (lane & 8) << 1;

    load_chunk(0, 0);

    for (int c = 0; c < NKC; c++) {
        const int cur = c & 1;
        if (c + 1 < NKC) {
            load_chunk(c + 1, (c + 1) & 1);
            asm volatile("cp.async.wait_group 1;" ::: "memory");
        } else {
            asm volatile("cp.async.wait_group 0;" ::: "memory");
        }
        __syncthreads();

        const uint32_t ab = sb + aoff[cur];
        const uint32_t bb = sb + boff[cur];
        #pragma unroll
        for (int kk = 0; kk < 4; kk++) {
            uint32_t afr[4][4];
            #pragma unroll
            for (int mi = 0; mi < 4; mi++) {
                uint32_t addr = ab + SWZ128((warp_m + mi * 16 + a_row) * 128
                                            + kk * 32 + a_kb);
                LDSM_X4(afr[mi][0], afr[mi][1], afr[mi][2], afr[mi][3], addr);
            }
            uint32_t bfr[8][2];
            #pragma unroll
            for (int nb2 = 0; nb2 < 4; nb2++) {
                uint32_t addr = bb + SWZ128((warp_n + nb2 * 16 + b_row) * 128
                                            + kk * 32 + b_kb);
                uint32_t r0, r1, r2, r3;
                LDSM_X4(r0, r1, r2, r3, addr);
                bfr[nb2 * 2 + 0][0] = r0; bfr[nb2 * 2 + 0][1] = r1;
                bfr[nb2 * 2 + 1][0] = r2; bfr[nb2 * 2 + 1][1] = r3;
            }
            #pragma unroll
            for (int mi = 0; mi < 4; mi++)
                #pragma unroll
                for (int nj = 0; nj < 8; nj++)
                    mma_bf16(acc[mi][nj], afr[mi], bfr[nj]);
        }
        __syncthreads();
    }

    // ---- Fused epilogue: per (row, 64-col warp chunk) sorted top-8 ----
    const float* c2s = reinterpret_cast<const float*>(smem + OFF_C2S);
    const int r0 = lane >> 2;
    const int cl = (lane & 3) * 2;
    const int chunk = blockIdx.x * 4 + (wid & 3);   // 0..255 within token

    #pragma unroll
    for (int mi = 0; mi < 4; mi++) {
        #pragma unroll
        for (int half = 0; half < 2; half++) {
            const int row = bm + warp_m + mi * 16 + r0 + half * 8;
            float bv[8]; int bix[8];
            // first 8 of this lane's 16 chunk values
            #pragma unroll
            for (int j = 0; j < 8; j++) {
                const int nj = j >> 1, p = j & 1;
                const int colc = warp_n + nj * 8 + cl + p;
                bv[j]  = 2.f * acc[mi][nj][half * 2 + p] - c2s[colc];
                bix[j] = bn + colc;
            }
            sort8_desc(bv, bix);
            // insert remaining 8 (single-element bubble, static indices)
            #pragma unroll
            for (int j = 8; j < 16; j++) {
                const int nj = j >> 1, p = j & 1;
                const int colc = warp_n + nj * 8 + cl + p;
                const float s = 2.f * acc[mi][nj][half * 2 + p] - c2s[colc];
                const int gidx = bn + colc;
                if (better(s, gidx, bv[7], bix[7])) {
                    bv[7] = s; bix[7] = gidx;
                    ce(bv[6],bix[6],bv[7],bix[7]); ce(bv[5],bix[5],bv[6],bix[6]);
                    ce(bv[4],bix[4],bv[5],bix[5]); ce(bv[3],bix[3],bv[4],bix[4]);
                    ce(bv[2],bix[2],bv[3],bix[3]); ce(bv[1],bix[1],bv[2],bix[2]);
                    ce(bv[0],bix[0],bv[1],bix[1]);
                }
            }
            // merge the 4 lanes sharing this row (lane xor 1, then xor 2)
            #pragma unroll
            for (int d = 1; d <= 2; d <<= 1) {
                float tv[8]; int ti[8];
                #pragma unroll
                for (int q = 0; q < 8; q++) {
                    tv[q] = __shfl_xor_sync(0xffffffffu, bv[q], d);
                    ti[q] = __shfl_xor_sync(0xffffffffu, bix[q], d);
                }
                merge_top8(bv, bix, tv, ti);
            }
            if ((lane & 3) == 0) {
                size_t base = ((size_t)row * NCHUNKS + chunk) * 8;
                #pragma unroll
                for (int k2 = 0; k2 < 8; k2++) {
                    g_pv[base + k2] = bv[k2];
                    g_pi[base + k2] = bix[k2];
                }
            }
        }
    }
}

// ---------------------------------------------------------------------------
// Merge 256 sorted-8 chunk lists -> top-32 candidates per token
// ---------------------------------------------------------------------------
__device__ __forceinline__ void merge_lists(
    const float* av, const int* ai, int la,
    const float* bv, const int* bi, int lb,
    float* ov, int* oi, int lo)
{
    int i = 0, j = 0;
    for (int o = 0; o < lo; o++) {
        bool ta;
        if (i >= la) ta = false;
        else if (j >= lb) ta = true;
        else ta = better(av[i], ai[i], bv[j], bi[j]);
        ov[o] = ta ? av[i] : bv[j];
        oi[o] = ta ? ai[i] : bi[j];
        if (ta) i++; else j++;
    }
}

__global__ __launch_bounds__(256) void reduce_kernel() {
    const int token = blockIdx.x;
    const int t = threadIdx.x;

    __shared__ float va[2048]; __shared__ int ia[2048];
    __shared__ float vb[2048]; __shared__ int ib[2048];

    size_t base = ((size_t)token * NCHUNKS + t) * 8;
    #pragma unroll
    for (int i = 0; i < 8; i++) { va[t * 8 + i] = g_pv[base + i]; ia[t * 8 + i] = g_pi[base + i]; }
    __syncthreads();

    if (t < 128)
        merge_lists(va + (2*t)*8, ia + (2*t)*8, 8, va + (2*t+1)*8, ia + (2*t+1)*8, 8,
                    vb + t*16, ib + t*16, 16);
    __syncthreads();
    if (t < 64)
        merge_lists(vb + (2*t)*16, ib + (2*t)*16, 16, vb + (2*t+1)*16, ib + (2*t+1)*16, 16,
                    va + t*32, ia + t*32, 32);
    __syncthreads();
    float* src_v = va; int* src_i = ia; float* dst_v = vb; int* dst_i = ib;
    for (int n = 32; n >= 1; n >>= 1) {
        if (t < n)
            merge_lists(src_v + (2*t)*32, src_i + (2*t)*32, 32,
                        src_v + (2*t+1)*32, src_i + (2*t+1)*32, 32,
                        dst_v + t*32, dst_i + t*32, 32);
        __syncthreads();
        float* tv = src_v; src_v = dst_v; dst_v = tv;
        int*   ti = src_i; src_i = dst_i; dst_i = ti;
    }
    if (t < NCAND) g_cand[token * NCAND + t] = src_i[t];
}

// ---------------------------------------------------------------------------
// Exact fp32 rescore of 32 candidates + top-8 select + gather/mean
// ---------------------------------------------------------------------------
__global__ __launch_bounds__(256) void rescore_kernel(
    const float* __restrict__ X, const float* __restrict__ CB,
    float* __restrict__ out, float* idsf, int* idsi, int write_main)
{
    const int token = blockIdx.x;
    const int tid = threadIdx.x;
    const int w = tid >> 5, lane = tid & 31;
    __shared__ float xs[DIM];
    __shared__ float cs[NCAND];
    __shared__ int   cid[NCAND];
    __shared__ int   sel[KSEL];

    reinterpret_cast<float4*>(xs)[tid] =
        reinterpret_cast<const float4*>(X + (size_t)token * DIM)[tid];
    if (tid < NCAND) cid[tid] = g_cand[token * NCAND + tid];
    __syncthreads();

    #pragma unroll
    for (int q = 0; q < 4; q++) {
        const int slot = w + q * 8;
        const int c = cid[slot];
        const float4* cp4 = reinterpret_cast<const float4*>(CB + (size_t)c * DIM);
        float acc = 0.f;
        #pragma unroll
        for (int u = 0; u < 8; u++) {
            float4 cv = cp4[lane + 32 * u];
            float4 xv = reinterpret_cast<const float4*>(xs)[lane + 32 * u];
            acc += xv.x * cv.x + xv.y * cv.y + xv.z * cv.z + xv.w * cv.w;
        }
        #pragma unroll
        for (int o = 16; o > 0; o >>= 1) acc += __shfl_down_sync(0xffffffffu, acc, o);
        if (lane == 0) cs[slot] = 2.f * acc - g_c2[c];
    }
    __syncthreads();

    if (tid == 0) {
        unsigned used = 0;
        #pragma unroll
        for (int k = 0; k < KSEL; k++) {
            float bvv = -INFINITY; int bii = 0x7fffffff; int bs = -1;
            for (int i = 0; i < NCAND; i++) {
                if (used & (1u << i)) continue;
                if (better(cs[i], cid[i], bvv, bii)) { bvv = cs[i]; bii = cid[i]; bs = i; }
            }
            used |= (1u << bs);
            sel[k] = bii;
            g_ids[token * KSEL + k] = bii;
            if (idsf) idsf[token * KSEL + k] = (float)bii;
            if (idsi) idsi[token * KSEL + k] = bii;
        }
    }
    __syncthreads();

    if (write_main) {
        float4 acc = make_float4(0.f, 0.f, 0.f, 0.f);
        #pragma unroll
        for (int k = 0; k < KSEL; k++) {
            float4 cv = reinterpret_cast<const float4*>(CB + (size_t)sel[k] * DIM)[tid];
            acc.x += cv.x; acc.y += cv.y; acc.z += cv.z; acc.w += cv.w;
        }
        float4 r = make_float4(acc.x * 0.125f, acc.y * 0.125f,
                               acc.z * 0.125f, acc.w * 0.125f);
        reinterpret_cast<float4*>(out + (size_t)token * DIM)[tid] = r;
    }
}

// ---------------------------------------------------------------------------
// Launch
// ---------------------------------------------------------------------------
extern "C" void kernel_launch(void* const* d_in, const int* in_sizes, int n_in,
                              void* d_out, int out_size) {
    const float* inputs   = (const float*)d_in[0];
    const float* codebook = (const float*)d_in[1];
    float* out = (float*)d_out;

    convX_kernel<<<TOKENS * DIM / 1024, 256>>>(inputs);
    convCB_c2_kernel<<<CODES, 256>>>(codebook);

    cudaFuncSetAttribute(gemm_cand_kernel,
                         cudaFuncAttributeMaxDynamicSharedMemorySize, GEMM_SMEM);
    gemm_cand_kernel<<<dim3(CODES / 256, TOKENS / 128), 256, GEMM_SMEM>>>();

    reduce_kernel<<<TOKENS, 256>>>();

    const int OUT_MAIN = TOKENS * DIM;
    const int OUT_IDS  = TOKENS * KSEL;
    float* idsf = nullptr; int* idsi = nullptr;
    int write_main = (out_size >= OUT_MAIN) ? 1 : 0;
    if (out_size == OUT_MAIN + OUT_IDS)      idsf = out + (size_t)OUT_MAIN;
    else if (out_size == OUT_IDS)            idsi = (int*)d_out;

    rescore_kernel<<<TOKENS, 256>>>(inputs, codebook, out, idsf, idsi, write_main);
}